// round 15
// baseline (speedup 1.0000x reference)
#include <cuda_runtime.h>
#include <math.h>

#define Bv 65536
#define Tv 64
#define Uv 8
#define NB 8   // batches per warp

// Precomputed state.
// g_wpk[p][th][j][i] = wflip[4p+j][th+16i], lane-packed so each lane reads
// its 16 weights as 4 consecutive float4s.
__device__ float  g_wpk[2][16][4][4];
__device__ float2 g_ab[Uv];         // (alpha*100, beta*10)

// ---------------------------------------------------------------------------
// Setup: per-channel constants once, then Kz, argmax -> t_idx, packed weights.
// ---------------------------------------------------------------------------
__global__ void setup_kernel(const float* __restrict__ alpha,
                             const float* __restrict__ beta,
                             const float* __restrict__ gammap,
                             const float* __restrict__ tauZ,
                             const float* __restrict__ nZ,
                             const float* __restrict__ tauC,
                             const float* __restrict__ nC) {
    __shared__ float Kz[Tv][Uv];
    __shared__ int   tidx[Uv];
    __shared__ float s_tc[Uv], s_nc[Uv], s_normc[Uv];
    __shared__ float s_tz[Uv], s_nz[Uv], s_normz[Uv];
    __shared__ float s_g[Uv];

    int tid = threadIdx.x;  // 512 threads

    if (tid < Uv) {
        int u = tid;
        float tau_c = tauC[u] * 100.0f;
        float n_c   = nC[u]   * 10.0f;
        float tau_z = tauZ[u] * 100.0f;
        float n_z   = nZ[u]   * 10.0f;
        s_tc[u] = tau_c;  s_nc[u] = n_c;
        s_tz[u] = tau_z;  s_nz[u] = n_z;
        s_g[u]  = gammap[u] * 10.0f;
        s_normc[u] = __expf(-(n_c + 1.0f) * __logf(tau_c) - lgammaf(n_c + 1.0f));
        s_normz[u] = __expf(-(n_z + 1.0f) * __logf(tau_z) - lgammaf(n_z + 1.0f));
        g_ab[u] = make_float2(alpha[u] * 100.0f, beta[u] * 10.0f);
    }
    __syncthreads();

    if (tid < Tv * Uv) {
        int t = tid / Uv;
        int u = tid % Uv;
        float tf = (float)t;
        float kc = 0.0f, kz2 = 0.0f;
        if (t > 0) {
            float lt = __logf(tf);
            kc  = __expf(s_nc[u] * lt - tf / s_tc[u]) * s_normc[u];
            kz2 = __expf(s_nz[u] * lt - tf / s_tz[u]) * s_normz[u];
        }
        float g = s_g[u];
        Kz[t][u] = g * kc + (1.0f - g) * kz2;
    }
    __syncthreads();

    if (tid < Uv) {
        int u = tid;
        float best = Kz[0][u];
        int bi = 0;
        for (int t = 1; t < Tv; ++t) {
            if (Kz[t][u] > best) { best = Kz[t][u]; bi = t; }  // first max wins
        }
        int ti = Tv - bi;                 // T - z_shift
        if (ti > Tv - 1) ti = Tv - 1;
        if (ti < 0) ti = 0;
        tidx[u] = ti;
    }
    __syncthreads();

    // Packed per-lane weights: flat tid = ((p*16+th)*4+j)*4+i
    if (tid < 512) {
        int i  = tid & 3;
        int j  = (tid >> 2) & 3;
        int th = (tid >> 4) & 15;
        int p  = (tid >> 8) & 1;
        int u  = 4 * p + j;
        int s  = th + 16 * i;
        int ti = tidx[u];
        float v = (s <= ti) ? Kz[ti - s][u] : 0.0f;
        ((float*)g_wpk)[tid] = v;
    }
}

// ---------------------------------------------------------------------------
// Main: one warp per NB batches.  Lane: th = lane>>1 (t-group), p = lane&1.
// Lane loads x[th+16i] i=0..3 (prefetched for all NB) -> serves BOTH the dot
// partials (channels 4p..4p+3) and the store pattern (t = 16i + lane>>1).
//   z[u] = dot(x, w[u]);  c[u] = a/(1+b*z);  out[.., t, u] = c[u]*x[t]
// ---------------------------------------------------------------------------
__global__ __launch_bounds__(256) void main_kernel(const float* __restrict__ x,
                                                   float* __restrict__ out) {
    int warp = blockIdx.x * (blockDim.x >> 5) + (threadIdx.x >> 5);
    int lane = threadIdx.x & 31;
    const unsigned FULL = 0xffffffffu;

    int p  = lane & 1;
    int th = lane >> 1;          // 0..15
    int b1 = (lane >> 1) & 1;    // th bit 0
    int b2 = (lane >> 2) & 1;    // th bit 1

    // Persistent packed weights: 16 floats = 4x LDG.128 (one-time)
    const float4* wp = (const float4*)&g_wpk[p][th][0][0];
    float4 wv0 = wp[0], wv1 = wp[1], wv2 = wp[2], wv3 = wp[3];

    int u = 4 * p + 2 * b1 + b2;        // channel this lane owns after reduce
    float2 ab = g_ab[u];

    size_t base = (size_t)warp * NB;
    const float* xb = x + base * Tv;
    float* ob = out + base * (Tv * Uv);

    // Prefetch ALL x values: 4 per batch, 32 total (MLP=32)
    float xs[NB][4];
#pragma unroll
    for (int n = 0; n < NB; ++n) {
#pragma unroll
        for (int i = 0; i < 4; ++i)
            xs[n][i] = __ldg(xb + n * Tv + th + 16 * i);
    }

#pragma unroll
    for (int n = 0; n < NB; ++n) {
        // Partial dots: channels 4p+j over this lane's 4 t-values
        float s0 = xs[n][0] * wv0.x;
        float s1 = xs[n][0] * wv1.x;
        float s2 = xs[n][0] * wv2.x;
        float s3 = xs[n][0] * wv3.x;
        s0 = fmaf(xs[n][1], wv0.y, s0);
        s1 = fmaf(xs[n][1], wv1.y, s1);
        s2 = fmaf(xs[n][1], wv2.y, s2);
        s3 = fmaf(xs[n][1], wv3.y, s3);
        s0 = fmaf(xs[n][2], wv0.z, s0);
        s1 = fmaf(xs[n][2], wv1.z, s1);
        s2 = fmaf(xs[n][2], wv2.z, s2);
        s3 = fmaf(xs[n][2], wv3.z, s3);
        s0 = fmaf(xs[n][3], wv0.w, s0);
        s1 = fmaf(xs[n][3], wv1.w, s1);
        s2 = fmaf(xs[n][3], wv2.w, s2);
        s3 = fmaf(xs[n][3], wv3.w, s3);

        // Packed butterfly over 16 th-groups: 5 SHFLs total.
        // Level mask=2 (th bit0): 4 channels -> 2
        float t0, t1;
        {
            float send0 = b1 ? s0 : s2;
            float send1 = b1 ? s1 : s3;
            float recv0 = __shfl_xor_sync(FULL, send0, 2);
            float recv1 = __shfl_xor_sync(FULL, send1, 2);
            t0 = (b1 ? s2 : s0) + recv0;
            t1 = (b1 ? s3 : s1) + recv1;
        }
        // Level mask=4 (th bit1): 2 -> 1
        float z;
        {
            float send = b2 ? t0 : t1;
            float recv = __shfl_xor_sync(FULL, send, 4);
            z = (b2 ? t1 : t0) + recv;
        }
        // Levels mask=8,16: plain reduce
        z += __shfl_xor_sync(FULL, z, 8);
        z += __shfl_xor_sync(FULL, z, 16);

        // Scale for this lane's channel
        float c = __fdividef(ab.x, fmaf(ab.y, z, 1.0f));

        // Gather the 4 channels this lane stores: U = 4*p + j
        // source lane = p | ((j>>1)<<1) | ((j&1)<<2)
        float c0 = __shfl_sync(FULL, c, p + 0);   // j=0
        float c1 = __shfl_sync(FULL, c, p + 4);   // j=1
        float c2 = __shfl_sync(FULL, c, p + 2);   // j=2
        float c3 = __shfl_sync(FULL, c, p + 6);   // j=3

        // Stores: element e = i*128 + lane*4 + j -> t = 16i + th, u = 4p + j.
        // x[t] is xs[n][i] (already in registers). Contiguous 512B per STG.
        float* on = ob + n * (Tv * Uv) + lane * 4;
#pragma unroll
        for (int i = 0; i < 4; ++i) {
            float xt = xs[n][i];
            *(float4*)(on + i * 128) =
                make_float4(xt * c0, xt * c1, xt * c2, xt * c3);
        }
    }
}

extern "C" void kernel_launch(void* const* d_in, const int* in_sizes, int n_in,
                              void* d_out, int out_size) {
    // Input order: inputs, alpha, beta, gamma, zeta, tauY, nY, tauZ, nZ, tauC, nC
    const float* inputs = (const float*)d_in[0];
    const float* alpha  = (const float*)d_in[1];
    const float* beta   = (const float*)d_in[2];
    const float* gammap = (const float*)d_in[3];
    const float* tauZ   = (const float*)d_in[7];
    const float* nZ     = (const float*)d_in[8];
    const float* tauC   = (const float*)d_in[9];
    const float* nC     = (const float*)d_in[10];
    float* out = (float*)d_out;

    setup_kernel<<<1, 512>>>(alpha, beta, gammap, tauZ, nZ, tauC, nC);

    // 65536 batches / (8 warps * NB) = 1024 blocks
    main_kernel<<<Bv / (8 * NB), 256>>>(inputs, out);
}

// round 16
// speedup vs baseline: 1.0656x; 1.0656x over previous
#include <cuda_runtime.h>
#include <math.h>

#define Bv 65536
#define Tv 64
#define Uv 8
#define NB 8   // batches per warp

// ---------------------------------------------------------------------------
// Single fused kernel. Each block redundantly computes the tiny setup
// (Kz filters, argmax shift, flipped+packed weights, a/b consts) in smem,
// then streams its NB*8 batches.
//
// Lane layout: th = lane>>1 (t-group 0..15), p = lane&1 (channel half).
// Lane loads x[th+16i], i=0..3 -> serves both dot partials (channels 4p..4p+3)
// and the store pattern (t = 16i + th).
// ---------------------------------------------------------------------------
__global__ __launch_bounds__(256) void fused_kernel(
    const float* __restrict__ x,
    float* __restrict__ out,
    const float* __restrict__ alpha,
    const float* __restrict__ beta,
    const float* __restrict__ gammap,
    const float* __restrict__ tauZ,
    const float* __restrict__ nZ,
    const float* __restrict__ tauC,
    const float* __restrict__ nC)
{
    __shared__ float  s_Kz[Tv][Uv];
    __shared__ float  s_w[2][16][4][4];   // packed: [p][th][j][i] = w[4p+j][th+16i]
    __shared__ float2 s_ab[Uv];
    __shared__ int    s_tidx[Uv];
    __shared__ float  s_tc[Uv], s_nc[Uv], s_normc[Uv];
    __shared__ float  s_tz[Uv], s_nz[Uv], s_normz[Uv];
    __shared__ float  s_g[Uv];

    int tid  = threadIdx.x;   // 256 threads
    int lane = tid & 31;

    // ---- Setup phase 1: per-channel constants (8 threads) ----
    if (tid < Uv) {
        int u = tid;
        float tau_c = tauC[u] * 100.0f;
        float n_c   = nC[u]   * 10.0f;
        float tau_z = tauZ[u] * 100.0f;
        float n_z   = nZ[u]   * 10.0f;
        s_tc[u] = tau_c;  s_nc[u] = n_c;
        s_tz[u] = tau_z;  s_nz[u] = n_z;
        s_g[u]  = gammap[u] * 10.0f;
        s_normc[u] = __expf(-(n_c + 1.0f) * __logf(tau_c) - lgammaf(n_c + 1.0f));
        s_normz[u] = __expf(-(n_z + 1.0f) * __logf(tau_z) - lgammaf(n_z + 1.0f));
        s_ab[u] = make_float2(alpha[u] * 100.0f, beta[u] * 10.0f);
    }
    __syncthreads();

    // ---- Setup phase 2: Kz[t][u] (512 entries, 2 per thread) ----
#pragma unroll
    for (int e = tid; e < Tv * Uv; e += 256) {
        int t = e / Uv;
        int u = e % Uv;
        float tf = (float)t;
        float kc = 0.0f, kz2 = 0.0f;
        if (t > 0) {
            float lt = __logf(tf);
            kc  = __expf(s_nc[u] * lt - tf / s_tc[u]) * s_normc[u];
            kz2 = __expf(s_nz[u] * lt - tf / s_tz[u]) * s_normz[u];
        }
        float g = s_g[u];
        s_Kz[t][u] = g * kc + (1.0f - g) * kz2;
    }
    __syncthreads();

    // ---- Setup phase 3: argmax -> t_idx (first max wins) ----
    if (tid < Uv) {
        int u = tid;
        float best = s_Kz[0][u];
        int bi = 0;
        for (int t = 1; t < Tv; ++t) {
            if (s_Kz[t][u] > best) { best = s_Kz[t][u]; bi = t; }
        }
        int ti = Tv - bi;                 // T - z_shift
        if (ti > Tv - 1) ti = Tv - 1;
        if (ti < 0) ti = 0;
        s_tidx[u] = ti;
    }
    __syncthreads();

    // ---- Setup phase 4: flipped + lane-packed weights ----
#pragma unroll
    for (int e = tid; e < 512; e += 256) {
        int i  = e & 3;
        int j  = (e >> 2) & 3;
        int th = (e >> 4) & 15;
        int p  = (e >> 8) & 1;
        int u  = 4 * p + j;
        int s  = th + 16 * i;
        int ti = s_tidx[u];
        s_w[p][th][j][i] = (s <= ti) ? s_Kz[ti - s][u] : 0.0f;
    }
    __syncthreads();

    // ---- Main streaming phase ----
    const unsigned FULL = 0xffffffffu;
    int p  = lane & 1;
    int th = lane >> 1;          // 0..15
    int b1 = (lane >> 1) & 1;    // th bit 0
    int b2 = (lane >> 2) & 1;    // th bit 1

    // Lane weights from smem (one-time)
    const float4* wp = (const float4*)&s_w[p][th][0][0];
    float4 wv0 = wp[0], wv1 = wp[1], wv2 = wp[2], wv3 = wp[3];

    int u = 4 * p + 2 * b1 + b2;        // channel this lane owns after reduce
    float2 ab = s_ab[u];

    int warp = blockIdx.x * 8 + (tid >> 5);
    size_t base = (size_t)warp * NB;
    const float* xb = x + base * Tv;
    float* ob = out + base * (Tv * Uv);

    // Prefetch ALL x values: 4 per batch, 32 total (MLP=32)
    float xs[NB][4];
#pragma unroll
    for (int n = 0; n < NB; ++n) {
#pragma unroll
        for (int i = 0; i < 4; ++i)
            xs[n][i] = __ldg(xb + n * Tv + th + 16 * i);
    }

#pragma unroll
    for (int n = 0; n < NB; ++n) {
        // Partial dots: channels 4p+j over this lane's 4 t-values
        float s0 = xs[n][0] * wv0.x;
        float s1 = xs[n][0] * wv1.x;
        float s2 = xs[n][0] * wv2.x;
        float s3 = xs[n][0] * wv3.x;
        s0 = fmaf(xs[n][1], wv0.y, s0);
        s1 = fmaf(xs[n][1], wv1.y, s1);
        s2 = fmaf(xs[n][1], wv2.y, s2);
        s3 = fmaf(xs[n][1], wv3.y, s3);
        s0 = fmaf(xs[n][2], wv0.z, s0);
        s1 = fmaf(xs[n][2], wv1.z, s1);
        s2 = fmaf(xs[n][2], wv2.z, s2);
        s3 = fmaf(xs[n][2], wv3.z, s3);
        s0 = fmaf(xs[n][3], wv0.w, s0);
        s1 = fmaf(xs[n][3], wv1.w, s1);
        s2 = fmaf(xs[n][3], wv2.w, s2);
        s3 = fmaf(xs[n][3], wv3.w, s3);

        // Packed butterfly over 16 th-groups: 5 SHFLs.
        float t0, t1;
        {
            float send0 = b1 ? s0 : s2;
            float send1 = b1 ? s1 : s3;
            float recv0 = __shfl_xor_sync(FULL, send0, 2);
            float recv1 = __shfl_xor_sync(FULL, send1, 2);
            t0 = (b1 ? s2 : s0) + recv0;
            t1 = (b1 ? s3 : s1) + recv1;
        }
        float z;
        {
            float send = b2 ? t0 : t1;
            float recv = __shfl_xor_sync(FULL, send, 4);
            z = (b2 ? t1 : t0) + recv;
        }
        z += __shfl_xor_sync(FULL, z, 8);
        z += __shfl_xor_sync(FULL, z, 16);

        // Scale for this lane's channel
        float c = __fdividef(ab.x, fmaf(ab.y, z, 1.0f));

        // Gather the 4 channels this lane stores: U = 4*p + j
        float c0 = __shfl_sync(FULL, c, p + 0);   // j=0
        float c1 = __shfl_sync(FULL, c, p + 4);   // j=1
        float c2 = __shfl_sync(FULL, c, p + 2);   // j=2
        float c3 = __shfl_sync(FULL, c, p + 6);   // j=3

        // Stores: element e = i*128 + lane*4 + j -> t = 16i + th, u = 4p + j.
        // x[t] = xs[n][i] (in registers). Contiguous 512B per STG across warp.
        float* on = ob + n * (Tv * Uv) + lane * 4;
#pragma unroll
        for (int i = 0; i < 4; ++i) {
            float xt = xs[n][i];
            *(float4*)(on + i * 128) =
                make_float4(xt * c0, xt * c1, xt * c2, xt * c3);
        }
    }
}

extern "C" void kernel_launch(void* const* d_in, const int* in_sizes, int n_in,
                              void* d_out, int out_size) {
    // Input order: inputs, alpha, beta, gamma, zeta, tauY, nY, tauZ, nZ, tauC, nC
    const float* inputs = (const float*)d_in[0];
    const float* alpha  = (const float*)d_in[1];
    const float* beta   = (const float*)d_in[2];
    const float* gammap = (const float*)d_in[3];
    const float* tauZ   = (const float*)d_in[7];
    const float* nZ     = (const float*)d_in[8];
    const float* tauC   = (const float*)d_in[9];
    const float* nC     = (const float*)d_in[10];
    float* out = (float*)d_out;

    // One kernel: 65536 batches / (8 warps * NB) = 1024 blocks
    fused_kernel<<<Bv / (8 * NB), 256>>>(inputs, out, alpha, beta, gammap,
                                         tauZ, nZ, tauC, nC);
}